// round 7
// baseline (speedup 1.0000x reference)
#include <cuda_runtime.h>
#include <cstdint>

#define NB     16
#define NROWS  128
#define NT     128
#define NH     32
#define NG     96
#define NE     64
#define NVOCAB 258
typedef unsigned long long u64;

// ---------------- static device scratch ----------------
__device__ __align__(16) float  g_proj[NVOCAB * NG];
__device__ __align__(16) float4 g_w4[3 * 2 * 3 * 8 * 32];      // [l][side][gate][chunk][j]
__device__ __align__(16) float  g_cbias[NG];
__device__ __align__(16) float  g_w64[NG];
__device__ __align__(16) float  g_wvt[NH * NVOCAB];            // w_out^T [k][v]
__device__ __align__(16) float4 g_hout4[NROWS * NT * 4 * 32];  // [rt][grp][j] = {b0..b3}
__device__ int g_flag[NROWS * 4];

// ---------------- helpers ----------------
__device__ __forceinline__ int ld_acq(const int* p) {
    int v; asm volatile("ld.acquire.gpu.s32 %0, [%1];" : "=r"(v) : "l"(p) : "memory"); return v;
}
__device__ __forceinline__ void st_rel(int* p, int v) {
    asm volatile("st.release.gpu.s32 [%0], %1;" :: "l"(p), "r"(v) : "memory");
}
__device__ __forceinline__ u64 dup2(float x) {
    u64 r; unsigned xi = __float_as_uint(x);
    asm("mov.b64 %0, {%1, %1};" : "=l"(r) : "r"(xi)); return r;
}
__device__ __forceinline__ u64 pack2(float a, float b) {
    u64 r; asm("mov.b64 %0, {%1, %2};" : "=l"(r) : "r"(__float_as_uint(a)), "r"(__float_as_uint(b)));
    return r;
}
__device__ __forceinline__ float2 unpk(u64 v) {
    unsigned lo, hi; asm("mov.b64 {%0, %1}, %2;" : "=r"(lo), "=r"(hi) : "l"(v));
    return make_float2(__uint_as_float(lo), __uint_as_float(hi));
}
__device__ __forceinline__ u64 fma2(u64 a, u64 b, u64 c) {
    u64 d; asm("fma.rn.f32x2 %0, %1, %2, %3;" : "=l"(d) : "l"(a), "l"(b), "l"(c)); return d;
}
__device__ __forceinline__ u64 add2(u64 a, u64 b) {
    u64 d; asm("add.rn.f32x2 %0, %1, %2;" : "=l"(d) : "l"(a), "l"(b)); return d;
}
__device__ __forceinline__ float tanh_ap(float x) {
    float y; asm("tanh.approx.f32 %0, %1;" : "=f"(y) : "f"(x)); return y;
}
__device__ __forceinline__ float sig_ap(float x) { return fmaf(tanh_ap(x * 0.5f), 0.5f, 0.5f); }

// ---------------- prep ----------------
__global__ void prep_kernel(
    const float* __restrict__ embed,
    const float* __restrict__ wih0, const float* __restrict__ whh0,
    const float* __restrict__ wih1, const float* __restrict__ whh1,
    const float* __restrict__ wih2, const float* __restrict__ whh2,
    const float* __restrict__ w_h2e, const float* __restrict__ b_h2e,
    const float* __restrict__ bih0, const float* __restrict__ w_out)
{
    const int v = blockIdx.x;
    const int g = threadIdx.x;       // 0..95
    if (v < NVOCAB) {
        float s = 0.0f;
        #pragma unroll 8
        for (int e = 0; e < NE; ++e) s = fmaf(embed[v * NE + e], wih0[g * 65 + e], s);
        g_proj[v * NG + g] = s;
    } else if (v == NVOCAB) {
        const int gate = g >> 5, j = g & 31;
        float cb = bih0[g];
        for (int e = 0; e < 65; ++e) cb = fmaf(wih0[g * 65 + e], b_h2e[e], cb);
        g_cbias[g] = cb;
        g_w64[g] = wih0[g * 65 + 64];
        float wc[NH];
        #pragma unroll
        for (int k = 0; k < NH; ++k) {
            float s = 0.0f;
            for (int e = 0; e < 65; ++e) s = fmaf(wih0[g * 65 + e], w_h2e[e * NH + k], s);
            wc[k] = s;
        }
        const float* Wm[3][2] = {{0, whh0}, {wih1, whh1}, {wih2, whh2}};
        #pragma unroll
        for (int c = 0; c < 8; ++c) {
            g_w4[(((0 * 2 + 0) * 3 + gate) * 8 + c) * 32 + j] =
                make_float4(wc[4*c], wc[4*c+1], wc[4*c+2], wc[4*c+3]);
            for (int l = 0; l < 3; ++l)
                for (int s_ = 0; s_ < 2; ++s_) {
                    const float* W = Wm[l][s_];
                    if (!W) continue;
                    g_w4[(((l * 2 + s_) * 3 + gate) * 8 + c) * 32 + j] =
                        make_float4(W[g*32+4*c], W[g*32+4*c+1], W[g*32+4*c+2], W[g*32+4*c+3]);
                }
        }
    } else {
        for (int i = g; i < NH * NVOCAB; i += NG) {
            int k = i / NVOCAB, vv = i % NVOCAB;
            g_wvt[i] = w_out[vv * NH + k];
        }
    }
}

__global__ void reset_kernel() {
    int i = threadIdx.x;
    if (i < NROWS * 4) g_flag[i] = 0;
}

// ---------------- one matvec side: 3 gates x 4 batches (f32x2 pairs) ----------------
__device__ __forceinline__ void mat_side(
    const float4* __restrict__ wb, int j, const float4* __restrict__ buf,
    u64* __restrict__ rz, u64* __restrict__ nn)
{
    #pragma unroll
    for (int c = 0; c < 8; ++c) {
        float4 wr = wb[(0 * 8 + c) * 32 + j];
        float4 wz = wb[(1 * 8 + c) * 32 + j];
        float4 wn = wb[(2 * 8 + c) * 32 + j];
        const float* fr = (const float*)&wr;
        const float* fz = (const float*)&wz;
        const float* fn = (const float*)&wn;
        const ulonglong2* bu = (const ulonglong2*)(buf + 4 * c);
        #pragma unroll
        for (int q = 0; q < 4; ++q) {
            ulonglong2 iv = bu[q];
            u64 d;
            d = dup2(fr[q]); rz[0] = fma2(d, iv.x, rz[0]); rz[1] = fma2(d, iv.y, rz[1]);
            d = dup2(fz[q]); rz[2] = fma2(d, iv.x, rz[2]); rz[3] = fma2(d, iv.y, rz[3]);
            d = dup2(fn[q]); nn[0] = fma2(d, iv.x, nn[0]); nn[1] = fma2(d, iv.y, nn[1]);
        }
    }
}

__device__ __forceinline__ float4 gru_epi(const u64* rz, const u64* ni, const u64* nh,
                                          float* __restrict__ hreg)
{
    float2 rv[2] = {unpk(rz[0]), unpk(rz[1])};
    float2 zv[2] = {unpk(rz[2]), unpk(rz[3])};
    float2 av[2] = {unpk(ni[0]), unpk(ni[1])};
    float2 bv[2] = {unpk(nh[0]), unpk(nh[1])};
    const float* rr = (const float*)rv; const float* zz = (const float*)zv;
    const float* ai = (const float*)av; const float* ah = (const float*)bv;
    float o[4];
    #pragma unroll
    for (int b = 0; b < 4; ++b) {
        float r = sig_ap(rr[b]);
        float z = sig_ap(zz[b]);
        float n = tanh_ap(fmaf(r, ah[b], ai[b]));
        o[b] = fmaf(z, hreg[b] - n, n);
        hreg[b] = o[b];
    }
    return make_float4(o[0], o[1], o[2], o[3]);
}

// ---------------- persistent warp-per-(row,group) wavefront ----------------
__global__ __launch_bounds__(128) void rnn_kernel(
    const int* __restrict__ x,
    const float* __restrict__ bhh0,
    const float* __restrict__ bih1, const float* __restrict__ bhh1,
    const float* __restrict__ bih2, const float* __restrict__ bhh2)
{
    __shared__ __align__(16) float4 sbuf[4][4][32];   // [warp][prev,h0,h1,h2][unit]
    __shared__ __align__(16) int4   toks[4][NT];      // [warp][t] = tokens {b0,b1,b2,b3}

    const int tid = threadIdx.x;
    const int w   = tid >> 5;
    const int j   = tid & 31;
    const int r   = blockIdx.x;
    const int b0  = w * 4;

    // ---- prologue: cache this row's tokens in smem (removes DRAM x-load from loop)
    #pragma unroll
    for (int i = 0; i < 4; ++i) {
        const int4* xp = (const int4*)(x + (b0 + i) * (NROWS * NT) + r * NT);
        int4 tv = __ldcg(&xp[j]);                     // tokens t = 4j..4j+3 for batch i
        ((int*)&toks[w][4 * j + 0])[i] = tv.x;
        ((int*)&toks[w][4 * j + 1])[i] = tv.y;
        ((int*)&toks[w][4 * j + 2])[i] = tv.z;
        ((int*)&toks[w][4 * j + 3])[i] = tv.w;
    }

    float4* prevb = &sbuf[w][0][0];
    float4* hb0   = &sbuf[w][1][0];
    float4* hb1   = &sbuf[w][2][0];
    float4* hb2   = &sbuf[w][3][0];
    const float4 z4 = make_float4(0.f, 0.f, 0.f, 0.f);
    prevb[j] = z4; hb0[j] = z4; hb1[j] = z4; hb2[j] = z4;
    float h0r[4] = {0,0,0,0}, h1r[4] = {0,0,0,0}, h2r[4] = {0,0,0,0};

    const float rf = (float)r * (2.0f / 128.0f) - 1.0f;
    const u64 dc_r0 = dup2(fmaf(rf, g_w64[j],      g_cbias[j])      + bhh0[j]);
    const u64 dc_z0 = dup2(fmaf(rf, g_w64[32 + j], g_cbias[32 + j]) + bhh0[32 + j]);
    const u64 dc_n0 = dup2(fmaf(rf, g_w64[64 + j], g_cbias[64 + j]));
    const u64 dc_h0 = dup2(bhh0[64 + j]);
    const u64 dc_r1 = dup2(bih1[j] + bhh1[j]);
    const u64 dc_z1 = dup2(bih1[32 + j] + bhh1[32 + j]);
    const u64 dc_n1 = dup2(bih1[64 + j]);
    const u64 dc_h1 = dup2(bhh1[64 + j]);
    const u64 dc_r2 = dup2(bih2[j] + bhh2[j]);
    const u64 dc_z2 = dup2(bih2[32 + j] + bhh2[32 + j]);
    const u64 dc_n2 = dup2(bih2[64 + j]);
    const u64 dc_h2 = dup2(bhh2[64 + j]);

    int*       myflag   = &g_flag[r * 4 + w];
    const int* prevflag = &g_flag[(r - 1) * 4 + w];
    __syncwarp();

    // ---- preload gate-init vectors for t = 0
    u64 c_r01, c_r23, c_z01, c_z23, c_n01, c_n23;
    {
        int4 tk = toks[w][0];
        const float* p0 = g_proj + tk.x * NG;
        const float* p1 = g_proj + tk.y * NG;
        const float* p2 = g_proj + tk.z * NG;
        const float* p3 = g_proj + tk.w * NG;
        c_r01 = add2(pack2(__ldg(&p0[j]),      __ldg(&p1[j])),      dc_r0);
        c_r23 = add2(pack2(__ldg(&p2[j]),      __ldg(&p3[j])),      dc_r0);
        c_z01 = add2(pack2(__ldg(&p0[32 + j]), __ldg(&p1[32 + j])), dc_z0);
        c_z23 = add2(pack2(__ldg(&p2[32 + j]), __ldg(&p3[32 + j])), dc_z0);
        c_n01 = add2(pack2(__ldg(&p0[64 + j]), __ldg(&p1[64 + j])), dc_n0);
        c_n23 = add2(pack2(__ldg(&p2[64 + j]), __ldg(&p3[64 + j])), dc_n0);
    }

    for (int t = 0; t < NT; ++t) {
        u64 rz[4], ni[2], nh[2];
        rz[0] = c_r01; rz[1] = c_r23; rz[2] = c_z01; rz[3] = c_z23;
        ni[0] = c_n01; ni[1] = c_n23; nh[0] = dc_h0; nh[1] = dc_h0;

        // issue next step's proj loads early (L1-hot; consumed at loop bottom)
        const int tn = (t < NT - 1) ? t + 1 : t;
        int4 tk = toks[w][tn];
        const float* p0 = g_proj + tk.x * NG;
        const float* p1 = g_proj + tk.y * NG;
        const float* p2 = g_proj + tk.z * NG;
        const float* p3 = g_proj + tk.w * NG;
        float q_r0 = __ldg(&p0[j]),      q_r1 = __ldg(&p1[j]);
        float q_r2 = __ldg(&p2[j]),      q_r3 = __ldg(&p3[j]);
        float q_z0 = __ldg(&p0[32 + j]), q_z1 = __ldg(&p1[32 + j]);
        float q_z2 = __ldg(&p2[32 + j]), q_z3 = __ldg(&p3[32 + j]);
        float q_n0 = __ldg(&p0[64 + j]), q_n1 = __ldg(&p1[64 + j]);
        float q_n2 = __ldg(&p2[64 + j]), q_n3 = __ldg(&p3[64 + j]);

        if (r > 0) {
            while (ld_acq(prevflag) < t + 1) { }
            prevb[j] = __ldcg(&g_hout4[(((r - 1) * NT + t) * 4 + w) * 32 + j]);
        }
        __syncwarp();

        // layer 0
        mat_side(g_w4 + 0 * 768, j, prevb, rz, ni);
        mat_side(g_w4 + 1 * 768, j, hb0,   rz, nh);
        float4 h0v = gru_epi(rz, ni, nh, h0r);
        __syncwarp(); hb0[j] = h0v; __syncwarp();

        // layer 1
        rz[0] = dc_r1; rz[1] = dc_r1; rz[2] = dc_z1; rz[3] = dc_z1;
        ni[0] = dc_n1; ni[1] = dc_n1; nh[0] = dc_h1; nh[1] = dc_h1;
        mat_side(g_w4 + 2 * 768, j, hb0, rz, ni);
        mat_side(g_w4 + 3 * 768, j, hb1, rz, nh);
        float4 h1v = gru_epi(rz, ni, nh, h1r);
        __syncwarp(); hb1[j] = h1v; __syncwarp();

        // layer 2
        rz[0] = dc_r2; rz[1] = dc_r2; rz[2] = dc_z2; rz[3] = dc_z2;
        ni[0] = dc_n2; ni[1] = dc_n2; nh[0] = dc_h2; nh[1] = dc_h2;
        mat_side(g_w4 + 4 * 768, j, hb1, rz, ni);
        mat_side(g_w4 + 5 * 768, j, hb2, rz, nh);
        float4 h2v = gru_epi(rz, ni, nh, h2r);
        __syncwarp(); hb2[j] = h2v;

        // fold next step's gate-init (proj values have arrived by now)
        c_r01 = add2(pack2(q_r0, q_r1), dc_r0);
        c_r23 = add2(pack2(q_r2, q_r3), dc_r0);
        c_z01 = add2(pack2(q_z0, q_z1), dc_z0);
        c_z23 = add2(pack2(q_z2, q_z3), dc_z0);
        c_n01 = add2(pack2(q_n0, q_n1), dc_n0);
        c_n23 = add2(pack2(q_n2, q_n3), dc_n0);

        // handoff: single STG.128 per lane + release flag
        __stcg(&g_hout4[((r * NT + t) * 4 + w) * 32 + j], h2v);
        __syncwarp();
        if (j == 0) st_rel(myflag, t + 1);
    }
}

// ---------------- epilogue: block = (group w, 8 cells), thread = vocab scalar ----------------
__global__ __launch_bounds__(256) void out_kernel(
    float* __restrict__ outp, const float* __restrict__ b_out)
{
    __shared__ __align__(16) u64 hp[NH][16];     // [k][cellpair]; cp = rt_i*2 + half
    const int tid = threadIdx.x;
    const int w   = blockIdx.x & 3;              // batch group (b = 4w + i)
    const int rt0 = (blockIdx.x >> 2) * 8;       // global rt = b-local cell index base

    {
        int k = tid & 31, rt_i = tid >> 5;       // 8 rt x 32 k = 256 threads
        float4 hv = __ldcg(&g_hout4[(((rt0 + rt_i)) * 4 + w) * 32 + k]);
        ulonglong2 pr;
        pr.x = pack2(hv.x, hv.y);                // batches 4w+0, 4w+1
        pr.y = pack2(hv.z, hv.w);                // batches 4w+2, 4w+3
        *(ulonglong2*)&hp[k][rt_i * 2] = pr;
    }
    __syncthreads();

    for (int v = tid; v < NVOCAB; v += 256) {
        u64 acc[16];
        const u64 bia = dup2(__ldg(&b_out[v]));
        #pragma unroll
        for (int cp = 0; cp < 16; ++cp) acc[cp] = bia;
        #pragma unroll
        for (int k = 0; k < NH; ++k) {
            const u64 wv = dup2(__ldg(&g_wvt[k * NVOCAB + v]));
            const ulonglong2* hk = (const ulonglong2*)hp[k];
            #pragma unroll
            for (int q = 0; q < 8; ++q) {
                ulonglong2 h2 = hk[q];
                acc[2 * q + 0] = fma2(wv, h2.x, acc[2 * q + 0]);
                acc[2 * q + 1] = fma2(wv, h2.y, acc[2 * q + 1]);
            }
        }
        #pragma unroll
        for (int rt_i = 0; rt_i < 8; ++rt_i) {
            long rt = rt0 + rt_i;
            float2 o0 = unpk(acc[rt_i * 2 + 0]);
            float2 o1 = unpk(acc[rt_i * 2 + 1]);
            outp[((long)(4 * w + 0) * (NROWS * NT) + rt) * NVOCAB + v] = o0.x;
            outp[((long)(4 * w + 1) * (NROWS * NT) + rt) * NVOCAB + v] = o0.y;
            outp[((long)(4 * w + 2) * (NROWS * NT) + rt) * NVOCAB + v] = o1.x;
            outp[((long)(4 * w + 3) * (NROWS * NT) + rt) * NVOCAB + v] = o1.y;
        }
    }
}

// ---------------- launch ----------------
extern "C" void kernel_launch(void* const* d_in, const int* in_sizes, int n_in,
                              void* d_out, int out_size)
{
    (void)in_sizes; (void)n_in; (void)out_size;
    const int*   x     = (const int*)  d_in[0];
    const float* embed = (const float*)d_in[1];
    const float* wih0  = (const float*)d_in[2];
    const float* whh0  = (const float*)d_in[3];
    const float* bih0  = (const float*)d_in[4];
    const float* bhh0  = (const float*)d_in[5];
    const float* wih1  = (const float*)d_in[6];
    const float* whh1  = (const float*)d_in[7];
    const float* bih1  = (const float*)d_in[8];
    const float* bhh1  = (const float*)d_in[9];
    const float* wih2  = (const float*)d_in[10];
    const float* whh2  = (const float*)d_in[11];
    const float* bih2  = (const float*)d_in[12];
    const float* bhh2  = (const float*)d_in[13];
    const float* w_h2e = (const float*)d_in[14];
    const float* b_h2e = (const float*)d_in[15];
    const float* w_out = (const float*)d_in[16];
    const float* b_out = (const float*)d_in[17];
    float* outp = (float*)d_out;

    prep_kernel<<<260, 96>>>(embed, wih0, whh0, wih1, whh1, wih2, whh2,
                             w_h2e, b_h2e, bih0, w_out);
    reset_kernel<<<1, 512>>>();
    rnn_kernel<<<NROWS, 128>>>(x, bhh0, bih1, bhh1, bih2, bhh2);
    out_kernel<<<(NB * NROWS * NT) / 32, 256>>>(outp, b_out);
}

// round 8
// speedup vs baseline: 1.1642x; 1.1642x over previous
#include <cuda_runtime.h>
#include <cstdint>

#define NB     16
#define NROWS  128
#define NT     128
#define NH     32
#define NG     96
#define NE     64
#define NVOCAB 258
typedef unsigned long long u64;

// ---------------- static device scratch ----------------
__device__ __align__(16) float  g_proj[NVOCAB * NG];
__device__ __align__(16) float4 g_w4[3 * 2 * 3 * 8 * 32];      // [l][side][gate][chunk][j]
__device__ __align__(16) float  g_cbias[NG];
__device__ __align__(16) float  g_w64[NG];
__device__ __align__(16) float  g_wvt[NH * NVOCAB];            // w_out^T [k][v]
__device__ __align__(16) float4 g_hout4[NROWS * NT * 4 * 32];  // [rt][grp][j] = {b0..b3}
__device__ int g_flag[NROWS * 4];                              // zero-init at load; reset restores

// ---------------- helpers ----------------
__device__ __forceinline__ int ld_acq(const int* p) {
    int v; asm volatile("ld.acquire.gpu.s32 %0, [%1];" : "=r"(v) : "l"(p) : "memory"); return v;
}
__device__ __forceinline__ void st_rel(int* p, int v) {
    asm volatile("st.release.gpu.s32 [%0], %1;" :: "l"(p), "r"(v) : "memory");
}
__device__ __forceinline__ u64 dup2(float x) {
    u64 r; unsigned xi = __float_as_uint(x);
    asm("mov.b64 %0, {%1, %1};" : "=l"(r) : "r"(xi)); return r;
}
__device__ __forceinline__ u64 pack2(float a, float b) {
    u64 r; asm("mov.b64 %0, {%1, %2};" : "=l"(r) : "r"(__float_as_uint(a)), "r"(__float_as_uint(b)));
    return r;
}
__device__ __forceinline__ float2 unpk(u64 v) {
    unsigned lo, hi; asm("mov.b64 {%0, %1}, %2;" : "=r"(lo), "=r"(hi) : "l"(v));
    return make_float2(__uint_as_float(lo), __uint_as_float(hi));
}
__device__ __forceinline__ u64 fma2(u64 a, u64 b, u64 c) {
    u64 d; asm("fma.rn.f32x2 %0, %1, %2, %3;" : "=l"(d) : "l"(a), "l"(b), "l"(c)); return d;
}
__device__ __forceinline__ float tanh_ap(float x) {
    float y; asm("tanh.approx.f32 %0, %1;" : "=f"(y) : "f"(x)); return y;
}
__device__ __forceinline__ float sig_ap(float x) { return fmaf(tanh_ap(x * 0.5f), 0.5f, 0.5f); }
__device__ __forceinline__ float dot4(float4 w, float4 v, float acc) {
    return fmaf(w.w, v.w, fmaf(w.z, v.z, fmaf(w.y, v.y, fmaf(w.x, v.x, acc))));
}

// ---------------- prep ----------------
__global__ void prep_kernel(
    const float* __restrict__ embed,
    const float* __restrict__ wih0, const float* __restrict__ whh0,
    const float* __restrict__ wih1, const float* __restrict__ whh1,
    const float* __restrict__ wih2, const float* __restrict__ whh2,
    const float* __restrict__ w_h2e, const float* __restrict__ b_h2e,
    const float* __restrict__ bih0, const float* __restrict__ w_out)
{
    const int v = blockIdx.x;
    const int g = threadIdx.x;       // 0..95
    if (v < NVOCAB) {
        float s = 0.0f;
        #pragma unroll 8
        for (int e = 0; e < NE; ++e) s = fmaf(embed[v * NE + e], wih0[g * 65 + e], s);
        g_proj[v * NG + g] = s;
    } else if (v == NVOCAB) {
        const int gate = g >> 5, j = g & 31;
        float cb = bih0[g];
        for (int e = 0; e < 65; ++e) cb = fmaf(wih0[g * 65 + e], b_h2e[e], cb);
        g_cbias[g] = cb;
        g_w64[g] = wih0[g * 65 + 64];
        float wc[NH];
        #pragma unroll
        for (int k = 0; k < NH; ++k) {
            float s = 0.0f;
            for (int e = 0; e < 65; ++e) s = fmaf(wih0[g * 65 + e], w_h2e[e * NH + k], s);
            wc[k] = s;
        }
        const float* Wm[3][2] = {{0, whh0}, {wih1, whh1}, {wih2, whh2}};
        #pragma unroll
        for (int c = 0; c < 8; ++c) {
            g_w4[(((0 * 2 + 0) * 3 + gate) * 8 + c) * 32 + j] =
                make_float4(wc[4*c], wc[4*c+1], wc[4*c+2], wc[4*c+3]);
            for (int l = 0; l < 3; ++l)
                for (int s_ = 0; s_ < 2; ++s_) {
                    const float* W = Wm[l][s_];
                    if (!W) continue;
                    g_w4[(((l * 2 + s_) * 3 + gate) * 8 + c) * 32 + j] =
                        make_float4(W[g*32+4*c], W[g*32+4*c+1], W[g*32+4*c+2], W[g*32+4*c+3]);
                }
        }
    } else {
        for (int i = g; i < NH * NVOCAB; i += NG) {
            int k = i / NVOCAB, vv = i % NVOCAB;
            g_wvt[i] = w_out[vv * NH + k];
        }
    }
}

__global__ void reset_kernel() {
    int i = threadIdx.x;
    if (i < NROWS * 4) g_flag[i] = 0;
}

// ---------------- persistent wavefront: CTA=(row,grp), thread=(unit j, batch b) ----------------
#define PADW 36
__global__ __launch_bounds__(128) void rnn_kernel(
    const int* __restrict__ x,
    const float* __restrict__ bhh0,
    const float* __restrict__ bih1, const float* __restrict__ bhh1,
    const float* __restrict__ bih2, const float* __restrict__ bhh2)
{
    __shared__ __align__(16) float prevsh[4][PADW];
    __shared__ __align__(16) float hsh[3][2][4][PADW];   // [layer][parity][b][unit]
    __shared__ int toksh[4][NT];

    const int tid = threadIdx.x;
    const int j   = tid >> 2;        // unit 0..31
    const int b   = tid & 3;         // batch-in-group
    const int r   = blockIdx.x >> 2;
    const int grp = blockIdx.x & 3;

    // prologue: tokens into smem; zero buffers
    for (int idx = tid; idx < 4 * NT; idx += 128) {
        int bb = idx >> 7, tt = idx & (NT - 1);
        toksh[bb][tt] = x[(grp * 4 + bb) * (NROWS * NT) + r * NT + tt];
    }
    prevsh[b][j] = 0.0f;
    for (int idx = tid; idx < 3 * 2 * 4 * PADW; idx += 128)
        (&hsh[0][0][0][0])[idx] = 0.0f;

    const float rf = (float)r * (2.0f / 128.0f) - 1.0f;
    // seeds (input-side + hidden-side biases folded; r,z use a single accumulator)
    const float c_r0 = fmaf(rf, g_w64[j],      g_cbias[j])      + bhh0[j];
    const float c_z0 = fmaf(rf, g_w64[32 + j], g_cbias[32 + j]) + bhh0[32 + j];
    const float c_n0 = fmaf(rf, g_w64[64 + j], g_cbias[64 + j]);
    const float c_h0 = bhh0[64 + j];
    const float c_r1 = bih1[j] + bhh1[j];
    const float c_z1 = bih1[32 + j] + bhh1[32 + j];
    const float c_n1 = bih1[64 + j];
    const float c_h1 = bhh1[64 + j];
    const float c_r2 = bih2[j] + bhh2[j];
    const float c_z2 = bih2[32 + j] + bhh2[32 + j];
    const float c_n2 = bih2[64 + j];
    const float c_h2 = bhh2[64 + j];

    float h0old = 0.f, h1old = 0.f, h2old = 0.f;

    int*       myflag   = &g_flag[r * 4 + grp];
    const int* prevflag = &g_flag[(r - 1) * 4 + grp];
    const float* prevbase = (const float*)g_hout4;   // layout: [rt][grp][j][b] scalar
    float*       outbase  = (float*)g_hout4;

    // per-layer weight base pointers: g_w4[(((l*2+s)*3+gate)*8+c)*32+j]
    const float4* w00 = g_w4 + ((0 * 6 + 0) * 3) * 256;  // l0 input side, gate-major
    const float4* w01 = g_w4 + ((0 * 6 + 3) * 0);        // placeholder (computed below)
    (void)w01; (void)w00;

    __syncthreads();

    for (int t = 0; t < NT; ++t) {
        const int p  = t & 1;
        const int q  = p ^ 1;
        const int tok = toksh[b][t];
        const float pr = __ldg(&g_proj[tok * NG + j]);
        const float pz = __ldg(&g_proj[tok * NG + 32 + j]);
        const float pn = __ldg(&g_proj[tok * NG + 64 + j]);

        if (r > 0) {
            while (ld_acq(prevflag) < t + 1) { }
            float pv = __ldcg(&prevbase[(((r - 1) * NT + t) * 4 + grp) * 128 + tid]);
            prevsh[b][j] = pv;
        }
        __syncthreads();                                  // bar A

        // ---- layer 0: input = prevsh, hidden = hsh[0][q] ----
        {
            float a_r = c_r0 + pr, a_z = c_z0 + pz, a_in = c_n0 + pn, a_hn = c_h0;
            const float4* wb = g_w4;                      // l=0,s=0 at gate*256 + c*32 + j
            const float4* hb = (const float4*)0;
            (void)hb;
            #pragma unroll
            for (int c = 0; c < 8; ++c) {
                float4 xin = *(const float4*)&prevsh[b][4 * c];
                float4 hin = *(const float4*)&hsh[0][q][b][4 * c];
                float4 wri = wb[0 * 256 + c * 32 + j];
                float4 wzi = wb[1 * 256 + c * 32 + j];
                float4 wni = wb[2 * 256 + c * 32 + j];
                float4 wrh = wb[3 * 256 + c * 32 + j];
                float4 wzh = wb[4 * 256 + c * 32 + j];
                float4 wnh = wb[5 * 256 + c * 32 + j];
                a_r  = dot4(wri, xin, a_r);  a_r  = dot4(wrh, hin, a_r);
                a_z  = dot4(wzi, xin, a_z);  a_z  = dot4(wzh, hin, a_z);
                a_in = dot4(wni, xin, a_in); a_hn = dot4(wnh, hin, a_hn);
            }
            float rr = sig_ap(a_r), zz = sig_ap(a_z);
            float nn = tanh_ap(fmaf(rr, a_hn, a_in));
            float hv = fmaf(zz, h0old - nn, nn);
            h0old = hv;
            hsh[0][p][b][j] = hv;
        }
        __syncthreads();                                  // bar B

        // ---- layer 1: input = hsh[0][p], hidden = hsh[1][q] ----
        {
            float a_r = c_r1, a_z = c_z1, a_in = c_n1, a_hn = c_h1;
            const float4* wb = g_w4 + 6 * 256;
            #pragma unroll
            for (int c = 0; c < 8; ++c) {
                float4 xin = *(const float4*)&hsh[0][p][b][4 * c];
                float4 hin = *(const float4*)&hsh[1][q][b][4 * c];
                float4 wri = wb[0 * 256 + c * 32 + j];
                float4 wzi = wb[1 * 256 + c * 32 + j];
                float4 wni = wb[2 * 256 + c * 32 + j];
                float4 wrh = wb[3 * 256 + c * 32 + j];
                float4 wzh = wb[4 * 256 + c * 32 + j];
                float4 wnh = wb[5 * 256 + c * 32 + j];
                a_r  = dot4(wri, xin, a_r);  a_r  = dot4(wrh, hin, a_r);
                a_z  = dot4(wzi, xin, a_z);  a_z  = dot4(wzh, hin, a_z);
                a_in = dot4(wni, xin, a_in); a_hn = dot4(wnh, hin, a_hn);
            }
            float rr = sig_ap(a_r), zz = sig_ap(a_z);
            float nn = tanh_ap(fmaf(rr, a_hn, a_in));
            float hv = fmaf(zz, h1old - nn, nn);
            h1old = hv;
            hsh[1][p][b][j] = hv;
        }
        __syncthreads();                                  // bar C

        // ---- layer 2: input = hsh[1][p], hidden = hsh[2][q] ----
        {
            float a_r = c_r2, a_z = c_z2, a_in = c_n2, a_hn = c_h2;
            const float4* wb = g_w4 + 12 * 256;
            #pragma unroll
            for (int c = 0; c < 8; ++c) {
                float4 xin = *(const float4*)&hsh[1][p][b][4 * c];
                float4 hin = *(const float4*)&hsh[2][q][b][4 * c];
                float4 wri = wb[0 * 256 + c * 32 + j];
                float4 wzi = wb[1 * 256 + c * 32 + j];
                float4 wni = wb[2 * 256 + c * 32 + j];
                float4 wrh = wb[3 * 256 + c * 32 + j];
                float4 wzh = wb[4 * 256 + c * 32 + j];
                float4 wnh = wb[5 * 256 + c * 32 + j];
                a_r  = dot4(wri, xin, a_r);  a_r  = dot4(wrh, hin, a_r);
                a_z  = dot4(wzi, xin, a_z);  a_z  = dot4(wzh, hin, a_z);
                a_in = dot4(wni, xin, a_in); a_hn = dot4(wnh, hin, a_hn);
            }
            float rr = sig_ap(a_r), zz = sig_ap(a_z);
            float nn = tanh_ap(fmaf(rr, a_hn, a_in));
            float hv = fmaf(zz, h2old - nn, nn);
            h2old = hv;
            hsh[2][p][b][j] = hv;
            __stcg(&outbase[((r * NT + t) * 4 + grp) * 128 + tid], hv);
        }
        __syncthreads();                                  // bar D
        if (tid == 0) st_rel(myflag, t + 1);
    }
}

// ---------------- epilogue (unchanged from R6: 161 us) ----------------
__global__ __launch_bounds__(256) void out_kernel(
    float* __restrict__ outp, const float* __restrict__ b_out)
{
    __shared__ __align__(16) u64 hp[NH][16];
    const int tid = threadIdx.x;
    const int w   = blockIdx.x & 3;
    const int rt0 = (blockIdx.x >> 2) * 8;

    {
        int k = tid & 31, rt_i = tid >> 5;
        float4 hv = __ldcg(&g_hout4[(((rt0 + rt_i)) * 4 + w) * 32 + k]);
        ulonglong2 pr;
        pr.x = pack2(hv.x, hv.y);
        pr.y = pack2(hv.z, hv.w);
        *(ulonglong2*)&hp[k][rt_i * 2] = pr;
    }
    __syncthreads();

    for (int v = tid; v < NVOCAB; v += 256) {
        u64 acc[16];
        const u64 bia = dup2(__ldg(&b_out[v]));
        #pragma unroll
        for (int cp = 0; cp < 16; ++cp) acc[cp] = bia;
        #pragma unroll
        for (int k = 0; k < NH; ++k) {
            const u64 wv = dup2(__ldg(&g_wvt[k * NVOCAB + v]));
            const ulonglong2* hk = (const ulonglong2*)hp[k];
            #pragma unroll
            for (int q = 0; q < 8; ++q) {
                ulonglong2 h2 = hk[q];
                acc[2 * q + 0] = fma2(wv, h2.x, acc[2 * q + 0]);
                acc[2 * q + 1] = fma2(wv, h2.y, acc[2 * q + 1]);
            }
        }
        #pragma unroll
        for (int rt_i = 0; rt_i < 8; ++rt_i) {
            long rt = rt0 + rt_i;
            float2 o0 = unpk(acc[rt_i * 2 + 0]);
            float2 o1 = unpk(acc[rt_i * 2 + 1]);
            outp[((long)(4 * w + 0) * (NROWS * NT) + rt) * NVOCAB + v] = o0.x;
            outp[((long)(4 * w + 1) * (NROWS * NT) + rt) * NVOCAB + v] = o0.y;
            outp[((long)(4 * w + 2) * (NROWS * NT) + rt) * NVOCAB + v] = o1.x;
            outp[((long)(4 * w + 3) * (NROWS * NT) + rt) * NVOCAB + v] = o1.y;
        }
    }
}

// ---------------- launch: order (prep, rnn, out, reset) ----------------
// g_flag is statically zero-initialized; reset LAST restores zeros for the next
// call/replay, so correctness holds and rnn_kernel lands at launch index 5
// (ncu -s 5 -c 1) for profiling.
extern "C" void kernel_launch(void* const* d_in, const int* in_sizes, int n_in,
                              void* d_out, int out_size)
{
    (void)in_sizes; (void)n_in; (void)out_size;
    const int*   x     = (const int*)  d_in[0];
    const float* embed = (const float*)d_in[1];
    const float* wih0  = (const float*)d_in[2];
    const float* whh0  = (const float*)d_in[3];
    const float* bih0  = (const float*)d_in[4];
    const float* bhh0  = (const float*)d_in[5];
    const float* wih1  = (const float*)d_in[6];
    const float* whh1  = (const float*)d_in[7];
    const float* bih1  = (const float*)d_in[8];
    const float* bhh1  = (const float*)d_in[9];
    const float* wih2  = (const float*)d_in[10];
    const float* whh2  = (const float*)d_in[11];
    const float* bih2  = (const float*)d_in[12];
    const float* bhh2  = (const float*)d_in[13];
    const float* w_h2e = (const float*)d_in[14];
    const float* b_h2e = (const float*)d_in[15];
    const float* w_out = (const float*)d_in[16];
    const float* b_out = (const float*)d_in[17];
    float* outp = (float*)d_out;

    prep_kernel<<<260, 96>>>(embed, wih0, whh0, wih1, whh1, wih2, whh2,
                             w_h2e, b_h2e, bih0, w_out);
    rnn_kernel<<<NROWS * 4, 128>>>(x, bhh0, bih1, bhh1, bih2, bhh2);
    out_kernel<<<(NB * NROWS * NT) / 32, 256>>>(outp, b_out);
    reset_kernel<<<1, 512>>>();
}